// round 16
// baseline (speedup 1.0000x reference)
#include <cuda_runtime.h>
#include <cuda_fp16.h>
#include <cuda_pipeline.h>
#include <mma.h>
#include <cstdint>

using namespace nvcuda;

#define NNODES 50000
#define MPAD   50048          // 391 * 128
#define EMAX   800000
#define DOUT   256
#define DIN    256

// ---------------------------------------------------------------------------
// Scratch (device globals)
// ---------------------------------------------------------------------------
__device__ __half g_h16[(size_t)MPAD * DOUT];    // x @ W in fp16 (gather source)
__device__ int   g_degi[NNODES];
__device__ int   g_off[NNODES];
__device__ int   g_cur[NNODES];
__device__ float g_dinv[NNODES];
__device__ int   g_csr[EMAX];
__device__ int   g_bsum[64];
__device__ __half g_a16[(size_t)MPAD * DIN];     // x in fp16
__device__ __half g_wt16[DOUT * DIN];            // W^T fp16 [n][k]

// ---------------------------------------------------------------------------
// Degree / CSR build
// ---------------------------------------------------------------------------
__global__ void k_zero(int n) {
    int i = blockIdx.x * blockDim.x + threadIdx.x;
    if (i < n) g_degi[i] = 0;
}
__global__ void k_count(const int* __restrict__ dst, int E) {
    int i = blockIdx.x * blockDim.x + threadIdx.x;
    if (i < E) atomicAdd(&g_degi[dst[i]], 1);
}

__global__ __launch_bounds__(1024) void k_scan1(int n) {
    __shared__ int wsum[32];
    int tid = threadIdx.x, lane = tid & 31, wid = tid >> 5;
    int i = blockIdx.x * 1024 + tid;
    int v = (i < n) ? g_degi[i] : 0;
    if (i < n) g_dinv[i] = rsqrtf((float)(v + 1));
    int sc = v;
    #pragma unroll
    for (int o = 1; o < 32; o <<= 1) {
        int t = __shfl_up_sync(0xffffffffu, sc, o);
        if (lane >= o) sc += t;
    }
    if (lane == 31) wsum[wid] = sc;
    __syncthreads();
    if (wid == 0) {
        int s = wsum[lane];
        #pragma unroll
        for (int o = 1; o < 32; o <<= 1) {
            int t = __shfl_up_sync(0xffffffffu, s, o);
            if (lane >= o) s += t;
        }
        wsum[lane] = s;
    }
    __syncthreads();
    int warpoff = (wid > 0) ? wsum[wid - 1] : 0;
    if (i < n) g_off[i] = warpoff + sc - v;
    if (tid == 0) g_bsum[blockIdx.x] = wsum[31];
}

__global__ void k_scan2(int nb) {
    __shared__ int w0tot;
    int t = threadIdx.x, lane = t & 31, wid = t >> 5;
    int v = (t < nb) ? g_bsum[t] : 0;
    int sc = v;
    #pragma unroll
    for (int o = 1; o < 32; o <<= 1) {
        int x = __shfl_up_sync(0xffffffffu, sc, o);
        if (lane >= o) sc += x;
    }
    if (wid == 0 && lane == 31) w0tot = sc;
    __syncthreads();
    int excl = sc - v + (wid ? w0tot : 0);
    if (t < nb) g_bsum[t] = excl;
}

__global__ __launch_bounds__(1024) void k_scan3(int n) {
    int i = blockIdx.x * 1024 + threadIdx.x;
    if (i >= n) return;
    int o = g_off[i] + g_bsum[blockIdx.x];
    g_off[i] = o;
    g_cur[i] = o;
}

__global__ void k_fill(const int* __restrict__ src,
                       const int* __restrict__ dst, int E) {
    int i = blockIdx.x * blockDim.x + threadIdx.x;
    if (i >= E) return;
    int d = dst[i];
    int pos = atomicAdd(&g_cur[d], 1);
    g_csr[pos] = src[i];
}

// ---------------------------------------------------------------------------
// Prep: x -> fp16, W -> fp16 W^T
// ---------------------------------------------------------------------------
__global__ void k_split(const float* __restrict__ x, int M) {
    int i = blockIdx.x * blockDim.x + threadIdx.x;   // uint4 index (8 fp16)
    int total = MPAD * DIN / 8;
    if (i >= total) return;
    int row = i >> 5;
    uint32_t h[4];
    if (row < M) {
        const float4* p = (const float4*)(x + ((size_t)i << 3));
        float4 v0 = p[0], v1 = p[1];
        __half2 h0 = __floats2half2_rn(v0.x, v0.y);
        __half2 h1 = __floats2half2_rn(v0.z, v0.w);
        __half2 h2 = __floats2half2_rn(v1.x, v1.y);
        __half2 h3 = __floats2half2_rn(v1.z, v1.w);
        h[0] = *(uint32_t*)&h0; h[1] = *(uint32_t*)&h1;
        h[2] = *(uint32_t*)&h2; h[3] = *(uint32_t*)&h3;
    } else {
        h[0] = h[1] = h[2] = h[3] = 0;
    }
    ((uint4*)g_a16)[i] = make_uint4(h[0], h[1], h[2], h[3]);
}

__global__ void k_wt(const float* __restrict__ W) {
    int i = blockIdx.x * blockDim.x + threadIdx.x;   // n*256 + k
    if (i >= DIN * DOUT) return;
    int n = i >> 8, k = i & 255;
    g_wt16[i] = __float2half_rn(W[k * DOUT + n]);
}

// ---------------------------------------------------------------------------
// WMMA GEMM half (fp16 1-pass): 128 output columns starting at nbase.
// ---------------------------------------------------------------------------
#define LDS 40
#define STAGE_ELEMS (128 * LDS)
#define STAGE_TOTAL (2 * STAGE_ELEMS)
#define SOUT_LD 132
#define SMEM_BYTES 69632

__global__ __launch_bounds__(256, 2) void k_gemm_wmma(int nbase) {
    extern __shared__ __align__(16) __half smd[];

    const int tid = threadIdx.x;
    const int w = tid >> 5;
    const int warp_m = w & 3;
    const int warp_n = w >> 2;
    const int Rbase = blockIdx.x * 128;
    const int Nbase = nbase;

    const int idx0 = tid * 2;
    const int r0 = idx0 >> 2, seg0 = idx0 & 3;
    const int r1 = (idx0 + 1) >> 2, seg1 = (idx0 + 1) & 3;

    auto prefetch = [&](int kc, int stage) {
        __half* dA = smd + stage * STAGE_TOTAL;
        __half* dB = dA + STAGE_ELEMS;
        __pipeline_memcpy_async(dA + r0 * LDS + seg0 * 8,
            (const uint4*)g_a16 + (size_t)(Rbase + r0) * 32 + kc * 4 + seg0, 16);
        __pipeline_memcpy_async(dA + r1 * LDS + seg1 * 8,
            (const uint4*)g_a16 + (size_t)(Rbase + r1) * 32 + kc * 4 + seg1, 16);
        __pipeline_memcpy_async(dB + r0 * LDS + seg0 * 8,
            (const uint4*)g_wt16 + (size_t)(Nbase + r0) * 32 + kc * 4 + seg0, 16);
        __pipeline_memcpy_async(dB + r1 * LDS + seg1 * 8,
            (const uint4*)g_wt16 + (size_t)(Nbase + r1) * 32 + kc * 4 + seg1, 16);
        __pipeline_commit();
    };

    wmma::fragment<wmma::accumulator, 16, 16, 16, float> acc[2][4];
    #pragma unroll
    for (int mi = 0; mi < 2; mi++)
        #pragma unroll
        for (int ni = 0; ni < 4; ni++)
            wmma::fill_fragment(acc[mi][ni], 0.0f);

    prefetch(0, 0);

    for (int kc = 0; kc < 8; kc++) {
        if (kc < 7) prefetch(kc + 1, (kc + 1) & 1);
        __pipeline_wait_prior(kc < 7 ? 1 : 0);
        __syncthreads();

        __half* sA = smd + (kc & 1) * STAGE_TOTAL;
        __half* sB = sA + STAGE_ELEMS;

        #pragma unroll
        for (int kk = 0; kk < 32; kk += 16) {
            wmma::fragment<wmma::matrix_a, 16, 16, 16, __half, wmma::row_major> af[2];
            #pragma unroll
            for (int mi = 0; mi < 2; mi++)
                wmma::load_matrix_sync(af[mi], sA + (warp_m * 32 + mi * 16) * LDS + kk, LDS);
            wmma::fragment<wmma::matrix_b, 16, 16, 16, __half, wmma::col_major> bf[4];
            #pragma unroll
            for (int ni = 0; ni < 4; ni++)
                wmma::load_matrix_sync(bf[ni], sB + (warp_n * 64 + ni * 16) * LDS + kk, LDS);
            #pragma unroll
            for (int mi = 0; mi < 2; mi++)
                #pragma unroll
                for (int ni = 0; ni < 4; ni++)
                    wmma::mma_sync(acc[mi][ni], af[mi], bf[ni], acc[mi][ni]);
        }
        __syncthreads();
    }

    // ---- fp16 epilogue: frags -> padded smem tile -> coalesced writes ----
    float* sOut = (float*)smd;
    #pragma unroll
    for (int mi = 0; mi < 2; mi++)
        #pragma unroll
        for (int ni = 0; ni < 4; ni++)
            wmma::store_matrix_sync(
                sOut + (warp_m * 32 + mi * 16) * SOUT_LD + warp_n * 64 + ni * 16,
                acc[mi][ni], SOUT_LD, wmma::mem_row_major);
    __syncthreads();

    #pragma unroll
    for (int j = 0; j < 8; j++) {
        int c = j * 256 + tid;
        int row = c >> 4;
        int u = c & 15;
        const float* src = sOut + row * SOUT_LD + u * 8;
        __half2 h[4];
        #pragma unroll
        for (int q = 0; q < 4; q++)
            h[q] = __floats2half2_rn(src[q * 2], src[q * 2 + 1]);
        *(uint4*)(g_h16 + (size_t)(Rbase + row) * DOUT + Nbase + u * 8) =
            *(const uint4*)h;
    }
}

// ---------------------------------------------------------------------------
// Node kernel half v2: 2 rows per warp-step.
// Lanes 0-15 handle even edges, 16-31 odd edges; each lane loads a uint4
// (8 halves = 16B); 16 lanes cover one 256B row. Sub-warp partials combine
// via shfl_xor(16). Halves gather LDG count vs uint2-per-lane scheme.
// ---------------------------------------------------------------------------
__device__ __forceinline__ void fma8h(uint4 v, float s, float* acc) {
    const __half2* h = (const __half2*)&v;
    #pragma unroll
    for (int q = 0; q < 4; q++) {
        float2 f = __half22float2(h[q]);
        acc[2 * q]     = fmaf(f.x, s, acc[2 * q]);
        acc[2 * q + 1] = fmaf(f.y, s, acc[2 * q + 1]);
    }
}

__global__ __launch_bounds__(256) void k_node(float* __restrict__ out,
                                              const float* __restrict__ b,
                                              const float* __restrict__ gamma,
                                              const float* __restrict__ beta,
                                              const float* __restrict__ mean,
                                              const float* __restrict__ var,
                                              int n, int col_base) {
    int warp = (blockIdx.x * blockDim.x + threadIdx.x) >> 5;
    int lane = threadIdx.x & 31;
    if (warp >= n) return;

    const int sub = lane >> 4;          // 0: even edges, 1: odd edges
    const int l16 = lane & 15;
    const int node = warp;
    const int start = g_off[node];
    const int end   = start + g_degi[node];
    const size_t u4_off = (size_t)(col_base >> 3) + l16;   // uint4 idx in row

    float acc[8] = {0.f, 0.f, 0.f, 0.f, 0.f, 0.f, 0.f, 0.f};

    int e = start;
    // 16-edge unroll: this lane handles edges e + 2q + sub, q=0..7
    for (; e + 15 < end; e += 16) {
        int   s[8];
        float wg[8];
        uint4 v[8];
        #pragma unroll
        for (int q = 0; q < 8; q++) s[q] = g_csr[e + 2 * q + sub];
        #pragma unroll
        for (int q = 0; q < 8; q++) wg[q] = g_dinv[s[q]];
        #pragma unroll
        for (int q = 0; q < 8; q++)
            v[q] = __ldg((const uint4*)(g_h16 + (size_t)s[q] * DOUT) + u4_off);
        #pragma unroll
        for (int q = 0; q < 8; q++) fma8h(v[q], wg[q], acc);
    }
    // pair tail
    for (; e < end; e += 2) {
        int ee = e + sub;
        if (ee < end) {
            int s0 = g_csr[ee];
            float w0 = g_dinv[s0];
            uint4 v = __ldg((const uint4*)(g_h16 + (size_t)s0 * DOUT) + u4_off);
            fma8h(v, w0, acc);
        }
    }
    // self-loop on sub 0
    float di = g_dinv[node];
    if (sub == 0) {
        uint4 v = __ldg((const uint4*)(g_h16 + (size_t)node * DOUT) + u4_off);
        fma8h(v, di, acc);
    }

    // combine sub halves; all lanes end with the full sum
    #pragma unroll
    for (int k = 0; k < 8; k++) {
        acc[k] += __shfl_xor_sync(0xffffffffu, acc[k], 16);
        acc[k] *= di;
    }

    // lanes 0-15 write cols [col_base + 8*l16, +8)
    if (sub == 0) {
        #pragma unroll
        for (int g = 0; g < 2; g++) {
            int c4 = (col_base >> 2) + 2 * l16 + g;
            float4 bv = ((const float4*)b)[c4];
            float4 gv = ((const float4*)gamma)[c4];
            float4 tv = ((const float4*)beta)[c4];
            float4 mv = ((const float4*)mean)[c4];
            float4 vv = ((const float4*)var)[c4];
            const float* a = acc + g * 4;
            float4 r;
            float sx = gv.x * rsqrtf(vv.x + 1e-5f);
            float sy = gv.y * rsqrtf(vv.y + 1e-5f);
            float sz = gv.z * rsqrtf(vv.z + 1e-5f);
            float sw = gv.w * rsqrtf(vv.w + 1e-5f);
            r.x = fmaxf(fmaf(a[0] + bv.x - mv.x, sx, tv.x), 0.f);
            r.y = fmaxf(fmaf(a[1] + bv.y - mv.y, sy, tv.y), 0.f);
            r.z = fmaxf(fmaf(a[2] + bv.z - mv.z, sz, tv.z), 0.f);
            r.w = fmaxf(fmaf(a[3] + bv.w - mv.w, sw, tv.w), 0.f);
            ((float4*)(out + (size_t)node * DOUT))[c4] = r;
        }
    }
}

// ---------------------------------------------------------------------------
// Column-split pipeline:
//   main: wt -> split -> gemm0 -> gemm1 -> (csr) node1 -> (n0)
//   s2:   zero -> count -> scan1/2/3 -> fill  [ev_csr]
//   s3:   (ev_g0, ev_csr) node0  -- concurrent with gemm1
// ---------------------------------------------------------------------------
extern "C" void kernel_launch(void* const* d_in, const int* in_sizes, int n_in,
                              void* d_out, int out_size) {
    const float* x      = (const float*)d_in[0];
    const int*   ei     = (const int*)d_in[1];   // int32 (jax x64 disabled)
    const float* W      = (const float*)d_in[2];
    const float* b      = (const float*)d_in[3];
    const float* gamma  = (const float*)d_in[4];
    const float* beta   = (const float*)d_in[5];
    const float* rmean  = (const float*)d_in[6];
    const float* rvar   = (const float*)d_in[7];
    float* out = (float*)d_out;

    int N = in_sizes[0] / DIN;     // 50000
    int E = in_sizes[1] / 2;       // 800000
    const int* src = ei;
    const int* dst = ei + E;
    int nb = (N + 1023) / 1024;

    static cudaStream_t s2, s3;
    static cudaEvent_t ev_fork, ev_csr, ev_g0, ev_n0;
    static bool init_done = false;
    if (!init_done) {
        cudaFuncSetAttribute(k_gemm_wmma,
                             cudaFuncAttributeMaxDynamicSharedMemorySize,
                             SMEM_BYTES);
        cudaStreamCreateWithFlags(&s2, cudaStreamNonBlocking);
        cudaStreamCreateWithFlags(&s3, cudaStreamNonBlocking);
        cudaEventCreateWithFlags(&ev_fork, cudaEventDisableTiming);
        cudaEventCreateWithFlags(&ev_csr, cudaEventDisableTiming);
        cudaEventCreateWithFlags(&ev_g0, cudaEventDisableTiming);
        cudaEventCreateWithFlags(&ev_n0, cudaEventDisableTiming);
        init_done = true;
    }

    long long nthreads = (long long)N * 32;
    int node_blocks = (int)((nthreads + 255) / 256);
    dim3 ggrid(MPAD / 128, 1);

    // fork
    cudaEventRecord(ev_fork, 0);
    cudaStreamWaitEvent(s2, ev_fork, 0);
    cudaStreamWaitEvent(s3, ev_fork, 0);

    k_wt<<<(DIN * DOUT + 255) / 256, 256>>>(W);                    // launch 1
    int splitn = MPAD * DIN / 8;
    k_split<<<(splitn + 255) / 256, 256>>>(x, N);                  // launch 2
    k_zero<<<(N + 255) / 256, 256, 0, s2>>>(N);                    // launch 3

    k_gemm_wmma<<<ggrid, 256, SMEM_BYTES>>>(0);                    // launch 4 (profile)
    cudaEventRecord(ev_g0, 0);

    // CSR chain on s2
    k_count<<<(E + 255) / 256, 256, 0, s2>>>(dst, E);
    k_scan1<<<nb, 1024, 0, s2>>>(N);
    k_scan2<<<1, 64, 0, s2>>>(nb);
    k_scan3<<<nb, 1024, 0, s2>>>(N);
    k_fill<<<(E + 255) / 256, 256, 0, s2>>>(src, dst, E);
    cudaEventRecord(ev_csr, s2);

    // gemm1 on main, node0 on s3 (concurrent)
    k_gemm_wmma<<<ggrid, 256, SMEM_BYTES>>>(128);
    cudaStreamWaitEvent(s3, ev_g0, 0);
    cudaStreamWaitEvent(s3, ev_csr, 0);
    k_node<<<node_blocks, 256, 0, s3>>>(out, b, gamma, beta, rmean, rvar, N, 0);
    cudaEventRecord(ev_n0, s3);

    // node1 on main after gemm1 + csr
    cudaStreamWaitEvent(0, ev_csr, 0);
    k_node<<<node_blocks, 256, 0, 0>>>(out, b, gamma, beta, rmean, rvar, N, 128);

    // join node0 back into origin stream
    cudaStreamWaitEvent(0, ev_n0, 0);
}